// round 11
// baseline (speedup 1.0000x reference)
#include <cuda_runtime.h>
#include <cuda_fp16.h>
#include <math.h>
#include <stdint.h>

// ---------------------------------------------------------------------------
// Problem constants
// ---------------------------------------------------------------------------
#define B_TOT   2048
#define L_TOK   49
#define C_DIM   512
#define H_HEADS 16
#define HD_DIM  32
#define ROWS    (B_TOT * L_TOK)        // 100352 = 784 * 128

// Scratch (device globals; allocation-free per harness rules)
static __device__ unsigned short g_qkvh[(size_t)ROWS * 3 * C_DIM];
static __device__ unsigned short g_atth[(size_t)ROWS * C_DIM];
static __device__ unsigned short g_wqkvth[3 * C_DIM * C_DIM];
static __device__ unsigned short g_wprojth[C_DIM * C_DIM];
static __device__ float g_bm[64 * 16 * 49 * 56];

// ---------------------------------------------------------------------------
// Helpers
// ---------------------------------------------------------------------------
__device__ __forceinline__ uint32_t smem_u32(const void* p) {
    uint32_t a;
    asm("{ .reg .u64 t; cvta.to.shared.u64 t, %1; cvt.u32.u64 %0, t; }" : "=r"(a) : "l"(p));
    return a;
}

__device__ __forceinline__ void ldsm_x4(uint32_t addr, uint32_t& r0, uint32_t& r1,
                                        uint32_t& r2, uint32_t& r3) {
    asm volatile("ldmatrix.sync.aligned.m8n8.x4.shared.b16 {%0,%1,%2,%3}, [%4];"
                 : "=r"(r0), "=r"(r1), "=r"(r2), "=r"(r3) : "r"(addr));
}

__device__ __forceinline__ void ldsm_x4_t(uint32_t addr, uint32_t& r0, uint32_t& r1,
                                          uint32_t& r2, uint32_t& r3) {
    asm volatile("ldmatrix.sync.aligned.m8n8.x4.trans.shared.b16 {%0,%1,%2,%3}, [%4];"
                 : "=r"(r0), "=r"(r1), "=r"(r2), "=r"(r3) : "r"(addr));
}

__device__ __forceinline__ void cp_async16(uint32_t d, const void* s) {
    asm volatile("cp.async.cg.shared.global [%0], [%1], 16;" :: "r"(d), "l"(s) : "memory");
}
__device__ __forceinline__ void cp_async16z(uint32_t d, const void* s, uint32_t sz) {
    asm volatile("cp.async.cg.shared.global [%0], [%1], 16, %2;"
                 :: "r"(d), "l"(s), "r"(sz) : "memory");
}
#define CP_COMMIT() asm volatile("cp.async.commit_group;" ::: "memory")

#define MMA_F16(c, a0, a1, a2, a3, b0, b1)                                      \
    asm volatile(                                                               \
        "mma.sync.aligned.m16n8k16.row.col.f32.f16.f16.f32 "                    \
        "{%0,%1,%2,%3}, {%4,%5,%6,%7}, {%8,%9}, {%0,%1,%2,%3};\n"               \
        : "+f"((c)[0]), "+f"((c)[1]), "+f"((c)[2]), "+f"((c)[3])                \
        : "r"(a0), "r"(a1), "r"(a2), "r"(a3), "r"(b0), "r"(b1))

// ---------------------------------------------------------------------------
// Pre-pass kernels
// ---------------------------------------------------------------------------
__global__ void transpose_h(const float* __restrict__ W, __half* __restrict__ Wt,
                            int Kdim, int Ndim) {
    __shared__ float t[32][33];
    const int n0 = blockIdx.x * 32, k0 = blockIdx.y * 32;
    const int x = threadIdx.x, y = threadIdx.y;
    #pragma unroll
    for (int i = 0; i < 32; i += 8)
        t[y + i][x] = W[(size_t)(k0 + y + i) * Ndim + n0 + x];
    __syncthreads();
    #pragma unroll
    for (int i = 0; i < 32; i += 8)
        Wt[(size_t)(n0 + y + i) * Kdim + k0 + x] = __float2half_rn(t[x][y + i]);
}

__global__ void build_bm(const float* __restrict__ mask, const float* __restrict__ bias,
                         float* __restrict__ bm) {
    int idx = blockIdx.x * 256 + threadIdx.x;
    const int TOT = 64 * 16 * 49 * 56;
    if (idx >= TOT) return;
    int m = idx % 56;
    int r = idx / 56;
    int l = r % 49;
    int wh = r / 49;
    int h = wh % 16;
    int win = wh / 16;
    float v = 0.f;
    if (m < 49) {
        int lh = l / 7, lw = l - lh * 7;
        int mh = m / 7, mw = m - mh * 7;
        int ri = (lh - mh + 6) * 13 + (lw - mw + 6);
        v = bias[ri * 16 + h] + mask[(win * 49 + l) * 49 + m];
    }
    bm[idx] = v;
}

// ---------------------------------------------------------------------------
// GEMM1: C[M,N](fp16) = A[M,K](fp32, converted in-kernel) * Bt[N,K](fp16)^T.
// BM=BN=128, BK=32 halves (64B rows). B: 3-stage cp.async (8KB/stage).
// A: register prefetch (4 float4/thread) -> convert -> double-buffered fp16
// smem (2 x 8KB). 256 threads, warp tile 64x32, mma.m16n8k16.
// Swizzle (64B rows, 4 units): u ^ ((row>>1)&3)  [proven R8].
// ---------------------------------------------------------------------------
__global__ __launch_bounds__(256, 2)
void gemm_f32a(const float* __restrict__ A, const __half* __restrict__ Bt,
               __half* __restrict__ C, int M, int N, int K) {
    __shared__ __align__(16) char sA[2][8192];
    __shared__ __align__(16) char sB[3][8192];

    const int tid = threadIdx.x, lane = tid & 31, warp = tid >> 5;
    const int wm = warp >> 2, wn = warp & 3;
    const int m0 = blockIdx.y * 128, n0 = blockIdx.x * 128;

    // B cp.async mapping: row rb, units cb, cb+1
    const int rb = tid >> 1, cb = (tid & 1) * 2;
    const __half* bg = Bt + (size_t)(n0 + rb) * K + cb * 8;
    const uint32_t bd0 = (uint32_t)(rb * 64 + (((cb)     ^ ((rb >> 1) & 3)) << 4));
    const uint32_t bd1 = (uint32_t)(rb * 64 + (((cb + 1) ^ ((rb >> 1) & 3)) << 4));

    // A LDG mapping: row ra, f32 cols ca..ca+15 -> fp16 units ua, ua+1
    const int ra = tid >> 1, ca = (tid & 1) * 16, ua = (tid & 1) * 2;
    const float* ag = A + (size_t)(m0 + ra) * K + ca;
    const uint32_t ad0 = (uint32_t)(ra * 64 + (((ua)     ^ ((ra >> 1) & 3)) << 4));
    const uint32_t ad1 = (uint32_t)(ra * 64 + (((ua + 1) ^ ((ra >> 1) & 3)) << 4));

    uint32_t sAu[2], sBu[3];
    sAu[0] = smem_u32(sA[0]); sAu[1] = smem_u32(sA[1]);
    #pragma unroll
    for (int s = 0; s < 3; ++s) sBu[s] = smem_u32(sB[s]);

    const int rr = lane & 7;
    const int mA = (lane >> 3) & 1;
    const int kU = lane >> 4;

    float acc[16][4];
    #pragma unroll
    for (int i = 0; i < 16; ++i)
        #pragma unroll
        for (int j = 0; j < 4; ++j) acc[i][j] = 0.f;

    const int nK = K >> 5;   // 16 for K=512

    float4 pa0, pa1, pa2, pa3;
    // prologue: A tile 0 + B stages 0,1
    pa0 = *(const float4*)(ag + 0);
    pa1 = *(const float4*)(ag + 4);
    pa2 = *(const float4*)(ag + 8);
    pa3 = *(const float4*)(ag + 12);
    #pragma unroll
    for (int p = 0; p < 2; ++p) {
        cp_async16(sBu[p] + bd0, bg + p * 32);
        cp_async16(sBu[p] + bd1, bg + p * 32 + 8);
        CP_COMMIT();
    }
    {   // convert A tile 0 into buffer 0
        __half2 h0 = __floats2half2_rn(pa0.x, pa0.y), h1 = __floats2half2_rn(pa0.z, pa0.w);
        __half2 h2 = __floats2half2_rn(pa1.x, pa1.y), h3 = __floats2half2_rn(pa1.z, pa1.w);
        __half2 h4 = __floats2half2_rn(pa2.x, pa2.y), h5 = __floats2half2_rn(pa2.z, pa2.w);
        __half2 h6 = __floats2half2_rn(pa3.x, pa3.y), h7 = __floats2half2_rn(pa3.z, pa3.w);
        *(uint4*)(sA[0] + ad0) = make_uint4(*(uint32_t*)&h0, *(uint32_t*)&h1,
                                            *(uint32_t*)&h2, *(uint32_t*)&h3);
        *(uint4*)(sA[0] + ad1) = make_uint4(*(uint32_t*)&h4, *(uint32_t*)&h5,
                                            *(uint32_t*)&h6, *(uint32_t*)&h7);
    }

    for (int kt = 0; kt < nK; ++kt) {
        if (kt + 1 < nK) asm volatile("cp.async.wait_group 1;" ::: "memory");
        else             asm volatile("cp.async.wait_group 0;" ::: "memory");
        __syncthreads();

        if (kt + 1 < nK) {
            const float* an = ag + (kt + 1) * 32;
            pa0 = *(const float4*)(an + 0);
            pa1 = *(const float4*)(an + 4);
            pa2 = *(const float4*)(an + 8);
            pa3 = *(const float4*)(an + 12);
        }
        if (kt + 2 < nK) {
            uint32_t so = sBu[(kt + 2) % 3];
            cp_async16(so + bd0, bg + (kt + 2) * 32);
            cp_async16(so + bd1, bg + (kt + 2) * 32 + 8);
            CP_COMMIT();
        }

        const uint32_t aB = sAu[kt & 1];
        const uint32_t bB = sBu[kt % 3];

        #pragma unroll
        for (int ks = 0; ks < 2; ++ks) {
            uint32_t af[4][4];
            #pragma unroll
            for (int mt = 0; mt < 4; ++mt) {
                int r = wm * 64 + mt * 16 + mA * 8 + rr;
                int u = ks * 2 + kU;
                ldsm_x4(aB + (uint32_t)(r * 64 + ((u ^ ((r >> 1) & 3)) << 4)),
                        af[mt][0], af[mt][1], af[mt][2], af[mt][3]);
            }
            uint32_t bf[2][4];
            #pragma unroll
            for (int p = 0; p < 2; ++p) {
                int n = wn * 32 + p * 16 + kU * 8 + rr;
                int u = ks * 2 + mA;
                ldsm_x4(bB + (uint32_t)(n * 64 + ((u ^ ((n >> 1) & 3)) << 4)),
                        bf[p][0], bf[p][1], bf[p][2], bf[p][3]);
            }
            #pragma unroll
            for (int mt = 0; mt < 4; ++mt)
                #pragma unroll
                for (int nt = 0; nt < 4; ++nt)
                    MMA_F16(acc[mt * 4 + nt],
                            af[mt][0], af[mt][1], af[mt][2], af[mt][3],
                            bf[nt >> 1][(nt & 1) * 2], bf[nt >> 1][(nt & 1) * 2 + 1]);
        }

        if (kt + 1 < nK) {   // convert prefetched A into the other buffer
            char* dst = sA[(kt + 1) & 1];
            __half2 h0 = __floats2half2_rn(pa0.x, pa0.y), h1 = __floats2half2_rn(pa0.z, pa0.w);
            __half2 h2 = __floats2half2_rn(pa1.x, pa1.y), h3 = __floats2half2_rn(pa1.z, pa1.w);
            __half2 h4 = __floats2half2_rn(pa2.x, pa2.y), h5 = __floats2half2_rn(pa2.z, pa2.w);
            __half2 h6 = __floats2half2_rn(pa3.x, pa3.y), h7 = __floats2half2_rn(pa3.z, pa3.w);
            *(uint4*)(dst + ad0) = make_uint4(*(uint32_t*)&h0, *(uint32_t*)&h1,
                                              *(uint32_t*)&h2, *(uint32_t*)&h3);
            *(uint4*)(dst + ad1) = make_uint4(*(uint32_t*)&h4, *(uint32_t*)&h5,
                                              *(uint32_t*)&h6, *(uint32_t*)&h7);
        }
    }

    const int g = lane >> 2, t = lane & 3;
    #pragma unroll
    for (int mt = 0; mt < 4; ++mt) {
        #pragma unroll
        for (int nt = 0; nt < 4; ++nt) {
            const float* c = acc[mt * 4 + nt];
            int r = m0 + wm * 64 + mt * 16 + g;
            int cc = n0 + wn * 32 + nt * 8 + t * 2;
            *(__half2*)&C[(size_t)r * N + cc]       = __floats2half2_rn(c[0], c[1]);
            *(__half2*)&C[(size_t)(r + 8) * N + cc] = __floats2half2_rn(c[2], c[3]);
        }
    }
}

// ---------------------------------------------------------------------------
// GEMM2 (fp16 in, fp32 out): unchanged R9 kernel. BK=64, 3x32KB dynamic smem.
// ---------------------------------------------------------------------------
#define GSTG_B 32768
#define GB_HALF 16384
#define GSMEM (3 * GSTG_B)

__global__ __launch_bounds__(256, 2)
void gemm_h2(const __half* __restrict__ A, const __half* __restrict__ Bt,
             float* __restrict__ C, int M, int N, int K) {
    extern __shared__ __align__(16) char dsm[];

    const int tid = threadIdx.x, lane = tid & 31, warp = tid >> 5;
    const int wm = warp >> 2, wn = warp & 3;
    const int m0 = blockIdx.y * 128, n0 = blockIdx.x * 128;

    const int r_ld = tid >> 1;
    const int cb   = (tid & 1) * 4;
    const __half* ag = A  + (size_t)(m0 + r_ld) * K + cb * 8;
    const __half* bg = Bt + (size_t)(n0 + r_ld) * K + cb * 8;
    uint32_t adst[4], bdst[4];
    #pragma unroll
    for (int j = 0; j < 4; ++j) {
        adst[j] = (uint32_t)(r_ld * 128 + (((cb + j) ^ (r_ld & 7)) << 4));
        bdst[j] = GB_HALF + adst[j];
    }

    uint32_t sb[3];
    #pragma unroll
    for (int s = 0; s < 3; ++s) sb[s] = smem_u32(dsm) + s * GSTG_B;

    const int rr = lane & 7;
    const int mA = (lane >> 3) & 1;
    const int kU = lane >> 4;

    float acc[16][4];
    #pragma unroll
    for (int i = 0; i < 16; ++i)
        #pragma unroll
        for (int j = 0; j < 4; ++j) acc[i][j] = 0.f;

    const int nK = K >> 6;

    #pragma unroll
    for (int p = 0; p < 2; ++p) {
        #pragma unroll
        for (int j = 0; j < 4; ++j) {
            cp_async16(sb[p] + adst[j], ag + p * 64 + j * 8);
            cp_async16(sb[p] + bdst[j], bg + p * 64 + j * 8);
        }
        CP_COMMIT();
    }

    for (int kt = 0; kt < nK; ++kt) {
        if (kt + 1 < nK) asm volatile("cp.async.wait_group 1;" ::: "memory");
        else             asm volatile("cp.async.wait_group 0;" ::: "memory");
        __syncthreads();

        if (kt + 2 < nK) {
            uint32_t so = sb[(kt + 2) % 3];
            #pragma unroll
            for (int j = 0; j < 4; ++j) {
                cp_async16(so + adst[j], ag + (kt + 2) * 64 + j * 8);
                cp_async16(so + bdst[j], bg + (kt + 2) * 64 + j * 8);
            }
            CP_COMMIT();
        }

        const uint32_t aB = sb[kt % 3];
        const uint32_t bB = aB + GB_HALF;

        #pragma unroll
        for (int ks = 0; ks < 4; ++ks) {
            uint32_t af[4][4];
            #pragma unroll
            for (int mt = 0; mt < 4; ++mt) {
                int r = wm * 64 + mt * 16 + mA * 8 + rr;
                int u = ks * 2 + kU;
                ldsm_x4(aB + (uint32_t)(r * 128 + ((u ^ (r & 7)) << 4)),
                        af[mt][0], af[mt][1], af[mt][2], af[mt][3]);
            }
            uint32_t bf[2][4];
            #pragma unroll
            for (int p = 0; p < 2; ++p) {
                int n = wn * 32 + p * 16 + kU * 8 + rr;
                int u = ks * 2 + mA;
                ldsm_x4(bB + (uint32_t)(n * 128 + ((u ^ (n & 7)) << 4)),
                        bf[p][0], bf[p][1], bf[p][2], bf[p][3]);
            }
            #pragma unroll
            for (int mt = 0; mt < 4; ++mt)
                #pragma unroll
                for (int nt = 0; nt < 4; ++nt)
                    MMA_F16(acc[mt * 4 + nt],
                            af[mt][0], af[mt][1], af[mt][2], af[mt][3],
                            bf[nt >> 1][(nt & 1) * 2], bf[nt >> 1][(nt & 1) * 2 + 1]);
        }
    }

    const int g = lane >> 2, t = lane & 3;
    #pragma unroll
    for (int mt = 0; mt < 4; ++mt) {
        #pragma unroll
        for (int nt = 0; nt < 4; ++nt) {
            const float* c = acc[mt * 4 + nt];
            int r = m0 + wm * 64 + mt * 16 + g;
            int cc = n0 + wn * 32 + nt * 8 + t * 2;
            *(float2*)&C[(size_t)r * N + cc]       = make_float2(c[0], c[1]);
            *(float2*)&C[(size_t)(r + 8) * N + cc] = make_float2(c[2], c[3]);
        }
    }
}

// ---------------------------------------------------------------------------
// fp16 tensor-core attention. One CTA per (window b, head h); 128 thr, 4 warps.
// Smem: Q [64][64B] @0, K @4096, V [64][64B] @8192 (row-major, PV uses
// ldmatrix.trans), P [64][144B] @12288. All Q/K/V via cp.async zfill.
// ---------------------------------------------------------------------------
#define QO 0
#define KO 4096
#define VO 8192
#define PO 12288
#define ATT_SMEM (12288 + 64 * 144)

__global__ __launch_bounds__(128, 6)
void attn_h(const __half* __restrict__ qkv, const float* __restrict__ bm,
            __half* __restrict__ att) {
    __shared__ __align__(16) char smc[ATT_SMEM];
    const uint32_t sb = smem_u32(smc);

    const int b = blockIdx.x, h = blockIdx.y;
    const int tid = threadIdx.x, lane = tid & 31, w = tid >> 5;

    const __half* base = qkv + (size_t)b * L_TOK * 1536 + h * HD_DIM;

    // Q, K, V via cp.async with zfill for pad rows 49..63
    #pragma unroll
    for (int j = 0; j < 2; ++j) {
        int u = tid * 2 + j;
        int r = u >> 2, c = u & 3;
        uint32_t sz = (r < L_TOK) ? 16u : 0u;
        const __half* src = (r < L_TOK) ? (base + (size_t)r * 1536 + c * 8) : base;
        uint32_t dst = (uint32_t)(r * 64 + ((c ^ ((r >> 1) & 3)) << 4));
        cp_async16z(sb + QO + dst, src, sz);
        cp_async16z(sb + KO + dst, src + 512, sz);
        cp_async16z(sb + VO + dst, src + 1024, sz);
    }
    CP_COMMIT();
    asm volatile("cp.async.wait_group 0;" ::: "memory");
    __syncthreads();

    const int rr = lane & 7;
    const int mA = (lane >> 3) & 1;
    const int kU = lane >> 4;

    // ---- QK^T: warp w -> rows w*16..+16, cols 0..63 ----
    float sacc[8][4];
    #pragma unroll
    for (int j = 0; j < 8; ++j)
        #pragma unroll
        for (int r = 0; r < 4; ++r) sacc[j][r] = 0.f;

    #pragma unroll
    for (int ks = 0; ks < 2; ++ks) {
        uint32_t a[4];
        {
            int r = w * 16 + mA * 8 + rr;
            int u = ks * 2 + kU;
            ldsm_x4(sb + QO + (uint32_t)(r * 64 + ((u ^ ((r >> 1) & 3)) << 4)),
                    a[0], a[1], a[2], a[3]);
        }
        uint32_t bf[4][4];
        #pragma unroll
        for (int p = 0; p < 4; ++p) {
            int n = p * 16 + kU * 8 + rr;
            int u = ks * 2 + mA;
            ldsm_x4(sb + KO + (uint32_t)(n * 64 + ((u ^ ((n >> 1) & 3)) << 4)),
                    bf[p][0], bf[p][1], bf[p][2], bf[p][3]);
        }
        #pragma unroll
        for (int nt = 0; nt < 8; ++nt)
            MMA_F16(sacc[nt], a[0], a[1], a[2], a[3],
                    bf[nt >> 1][(nt & 1) * 2], bf[nt >> 1][(nt & 1) * 2 + 1]);
    }

    // ---- scale + (bias+mask) + softmax ----
    const int g = lane >> 2, t = lane & 3;
    const int l0 = w * 16 + g, l1 = l0 + 8;
    const int win = b & 63;
    const bool v0 = (l0 < L_TOK), v1 = (l1 < L_TOK);
    const int l0c = v0 ? l0 : 48, l1c = v1 ? l1 : 48;
    const float* bm0 = bm + (((size_t)win * 16 + h) * 49 + l0c) * 56;
    const float* bm1 = bm + (((size_t)win * 16 + h) * 49 + l1c) * 56;
    const float scale = 0.1767766952966369f;

    float mx0 = -1e30f, mx1 = -1e30f;
    #pragma unroll
    for (int j = 0; j < 8; ++j) {
        int ma = 8 * j + 2 * t;
        float* c = sacc[j];
        if (ma < L_TOK) {
            float2 ba = *(const float2*)&bm0[ma];
            float2 bb = *(const float2*)&bm1[ma];
            c[0] = v0 ? fmaf(c[0], scale, ba.x) : -1e30f;
            c[1] = (v0 && ma + 1 < L_TOK) ? fmaf(c[1], scale, ba.y) : -1e30f;
            c[2] = v1 ? fmaf(c[2], scale, bb.x) : -1e30f;
            c[3] = (v1 && ma + 1 < L_TOK) ? fmaf(c[3], scale, bb.y) : -1e30f;
        } else {
            c[0] = c[1] = c[2] = c[3] = -1e30f;
        }
        mx0 = fmaxf(mx0, fmaxf(c[0], c[1]));
        mx1 = fmaxf(mx1, fmaxf(c[2], c[3]));
    }
    mx0 = fmaxf(mx0, __shfl_xor_sync(0xffffffffu, mx0, 1));
    mx0 = fmaxf(mx0, __shfl_xor_sync(0xffffffffu, mx0, 2));
    mx1 = fmaxf(mx1, __shfl_xor_sync(0xffffffffu, mx1, 1));
    mx1 = fmaxf(mx1, __shfl_xor_sync(0xffffffffu, mx1, 2));

    float s0 = 0.f, s1 = 0.f;
    #pragma unroll
    for (int j = 0; j < 8; ++j) {
        float* c = sacc[j];
        c[0] = __expf(c[0] - mx0);
        c[1] = __expf(c[1] - mx0);
        c[2] = __expf(c[2] - mx1);
        c[3] = __expf(c[3] - mx1);
        s0 += c[0] + c[1];
        s1 += c[2] + c[3];
    }
    s0 += __shfl_xor_sync(0xffffffffu, s0, 1);
    s0 += __shfl_xor_sync(0xffffffffu, s0, 2);
    s1 += __shfl_xor_sync(0xffffffffu, s1, 1);
    s1 += __shfl_xor_sync(0xffffffffu, s1, 2);
    const float i0 = 1.f / s0, i1 = 1.f / s1;

    // P -> smem fp16 [64][144B]
    #pragma unroll
    for (int j = 0; j < 8; ++j) {
        float* c = sacc[j];
        int col = 8 * j + 2 * t;
        *(__half2*)(smc + PO + l0 * 144 + col * 2) = __floats2half2_rn(c[0] * i0, c[1] * i0);
        *(__half2*)(smc + PO + l1 * 144 + col * 2) = __floats2half2_rn(c[2] * i1, c[3] * i1);
    }
    __syncwarp();   // each warp reads back only its own rows of P

    // ---- O = P @ V  (V row-major, B-fragments via ldmatrix.trans) ----
    float oacc[4][4];
    #pragma unroll
    for (int nt = 0; nt < 4; ++nt)
        #pragma unroll
        for (int r = 0; r < 4; ++r) oacc[nt][r] = 0.f;

    #pragma unroll
    for (int ks = 0; ks < 4; ++ks) {
        uint32_t a[4];
        {
            int r = w * 16 + mA * 8 + rr;
            int u = ks * 2 + kU;
            ldsm_x4(sb + PO + (uint32_t)(r * 144 + u * 16), a[0], a[1], a[2], a[3]);
        }
        uint32_t bf[2][4];
        #pragma unroll
        for (int p = 0; p < 2; ++p) {
            int vr = ks * 16 + mA * 8 + rr;      // V source row (= k index)
            int u  = p * 2 + kU;                 // d-unit
            ldsm_x4_t(sb + VO + (uint32_t)(vr * 64 + ((u ^ ((vr >> 1) & 3)) << 4)),
                      bf[p][0], bf[p][1], bf[p][2], bf[p][3]);
        }
        #pragma unroll
        for (int nt = 0; nt < 4; ++nt)
            MMA_F16(oacc[nt], a[0], a[1], a[2], a[3],
                    bf[nt >> 1][(nt & 1) * 2], bf[nt >> 1][(nt & 1) * 2 + 1]);
    }

    // ---- write merged-head output (fp16, feeds proj GEMM) ----
    __half* orow0 = att + ((size_t)b * L_TOK + l0) * C_DIM + h * HD_DIM;
    __half* orow1 = orow0 + (size_t)8 * C_DIM;
    #pragma unroll
    for (int nt = 0; nt < 4; ++nt) {
        int d = nt * 8 + t * 2;
        if (v0) *(__half2*)(orow0 + d) = __floats2half2_rn(oacc[nt][0], oacc[nt][1]);
        if (v1) *(__half2*)(orow1 + d) = __floats2half2_rn(oacc[nt][2], oacc[nt][3]);
    }
}

// ---------------------------------------------------------------------------
// kernel_launch
// ---------------------------------------------------------------------------
extern "C" void kernel_launch(void* const* d_in, const int* in_sizes, int n_in,
                              void* d_out, int out_size) {
    const float* x     = (const float*)d_in[0];
    const float* mask  = (const float*)d_in[1];
    const float* bias  = (const float*)d_in[2];
    const float* wqkv  = (const float*)d_in[3];
    const float* wproj = (const float*)d_in[4];
    float*       out   = (float*)d_out;

    void *qkvh, *atth, *wqkvth, *wprojth, *bm;
    cudaGetSymbolAddress(&qkvh, g_qkvh);
    cudaGetSymbolAddress(&atth, g_atth);
    cudaGetSymbolAddress(&wqkvth, g_wqkvth);
    cudaGetSymbolAddress(&wprojth, g_wprojth);
    cudaGetSymbolAddress(&bm, g_bm);

    cudaFuncSetAttribute(gemm_h2, cudaFuncAttributeMaxDynamicSharedMemorySize, GSMEM);

    // 0) Pre-passes (x conversion now fused into gemm_f32a)
    transpose_h<<<dim3(1536 / 32, 512 / 32), dim3(32, 8)>>>(wqkv, (__half*)wqkvth, C_DIM, 3 * C_DIM);
    transpose_h<<<dim3(512 / 32, 512 / 32), dim3(32, 8)>>>(wproj, (__half*)wprojth, C_DIM, C_DIM);
    const int bmTot = 64 * 16 * 49 * 56;
    build_bm<<<(bmTot + 255) / 256, 256>>>(mask, bias, (float*)bm);

    // 1) QKV projection: reads f32 x directly, converts in-kernel
    gemm_f32a<<<dim3(1536 / 128, ROWS / 128), 256>>>(
        x, (const __half*)wqkvth, (__half*)qkvh, ROWS, 3 * C_DIM, C_DIM);

    // 2) Windowed attention
    attn_h<<<dim3(B_TOT, H_HEADS), 128>>>((const __half*)qkvh, (const float*)bm, (__half*)atth);

    // 3) Output projection (fp32 out)
    gemm_h2<<<dim3(C_DIM / 128, ROWS / 128), 256, GSMEM>>>(
        (const __half*)atth, (const __half*)wprojth, out, ROWS, C_DIM, C_DIM);
}

// round 12
// speedup vs baseline: 1.1070x; 1.1070x over previous
#include <cuda_runtime.h>
#include <cuda_fp16.h>
#include <math.h>
#include <stdint.h>

// ---------------------------------------------------------------------------
// Problem constants
// ---------------------------------------------------------------------------
#define B_TOT   2048
#define L_TOK   49
#define C_DIM   512
#define H_HEADS 16
#define HD_DIM  32
#define ROWS    (B_TOT * L_TOK)        // 100352 = 784 * 128

// Scratch (device globals; allocation-free per harness rules)
static __device__ unsigned short g_xh[(size_t)ROWS * C_DIM];
static __device__ unsigned short g_qkvh[(size_t)ROWS * 3 * C_DIM];
static __device__ unsigned short g_atth[(size_t)ROWS * C_DIM];
static __device__ unsigned short g_wqkvth[3 * C_DIM * C_DIM];
static __device__ unsigned short g_wprojth[C_DIM * C_DIM];
static __device__ float g_bm[64 * 16 * 49 * 56];

// ---------------------------------------------------------------------------
// Helpers
// ---------------------------------------------------------------------------
__device__ __forceinline__ uint32_t smem_u32(const void* p) {
    uint32_t a;
    asm("{ .reg .u64 t; cvta.to.shared.u64 t, %1; cvt.u32.u64 %0, t; }" : "=r"(a) : "l"(p));
    return a;
}

__device__ __forceinline__ void ldsm_x4(uint32_t addr, uint32_t& r0, uint32_t& r1,
                                        uint32_t& r2, uint32_t& r3) {
    asm volatile("ldmatrix.sync.aligned.m8n8.x4.shared.b16 {%0,%1,%2,%3}, [%4];"
                 : "=r"(r0), "=r"(r1), "=r"(r2), "=r"(r3) : "r"(addr));
}

__device__ __forceinline__ void ldsm_x4_t(uint32_t addr, uint32_t& r0, uint32_t& r1,
                                          uint32_t& r2, uint32_t& r3) {
    asm volatile("ldmatrix.sync.aligned.m8n8.x4.trans.shared.b16 {%0,%1,%2,%3}, [%4];"
                 : "=r"(r0), "=r"(r1), "=r"(r2), "=r"(r3) : "r"(addr));
}

__device__ __forceinline__ void cp_async16(uint32_t d, const void* s) {
    asm volatile("cp.async.cg.shared.global [%0], [%1], 16;" :: "r"(d), "l"(s) : "memory");
}
__device__ __forceinline__ void cp_async16z(uint32_t d, const void* s, uint32_t sz) {
    asm volatile("cp.async.cg.shared.global [%0], [%1], 16, %2;"
                 :: "r"(d), "l"(s), "r"(sz) : "memory");
}
#define CP_COMMIT() asm volatile("cp.async.commit_group;" ::: "memory")

#define MMA_F16(c, a0, a1, a2, a3, b0, b1)                                      \
    asm volatile(                                                               \
        "mma.sync.aligned.m16n8k16.row.col.f32.f16.f16.f32 "                    \
        "{%0,%1,%2,%3}, {%4,%5,%6,%7}, {%8,%9}, {%0,%1,%2,%3};\n"               \
        : "+f"((c)[0]), "+f"((c)[1]), "+f"((c)[2]), "+f"((c)[3])                \
        : "r"(a0), "r"(a1), "r"(a2), "r"(a3), "r"(b0), "r"(b1))

// ---------------------------------------------------------------------------
// Pre-pass kernels
// ---------------------------------------------------------------------------
__global__ void f32_to_f16(const float4* __restrict__ in, __half2* __restrict__ out, int n4) {
    int i = blockIdx.x * blockDim.x + threadIdx.x;
    if (i < n4) {
        float4 v = in[i];
        out[2 * i]     = __floats2half2_rn(v.x, v.y);
        out[2 * i + 1] = __floats2half2_rn(v.z, v.w);
    }
}

__global__ void transpose_h(const float* __restrict__ W, __half* __restrict__ Wt,
                            int Kdim, int Ndim) {
    __shared__ float t[32][33];
    const int n0 = blockIdx.x * 32, k0 = blockIdx.y * 32;
    const int x = threadIdx.x, y = threadIdx.y;
    #pragma unroll
    for (int i = 0; i < 32; i += 8)
        t[y + i][x] = W[(size_t)(k0 + y + i) * Ndim + n0 + x];
    __syncthreads();
    #pragma unroll
    for (int i = 0; i < 32; i += 8)
        Wt[(size_t)(n0 + y + i) * Kdim + k0 + x] = __float2half_rn(t[x][y + i]);
}

__global__ void build_bm(const float* __restrict__ mask, const float* __restrict__ bias,
                         float* __restrict__ bm) {
    int idx = blockIdx.x * 256 + threadIdx.x;
    const int TOT = 64 * 16 * 49 * 56;
    if (idx >= TOT) return;
    int m = idx % 56;
    int r = idx / 56;
    int l = r % 49;
    int wh = r / 49;
    int h = wh % 16;
    int win = wh / 16;
    float v = 0.f;
    if (m < 49) {
        int lh = l / 7, lw = l - lh * 7;
        int mh = m / 7, mw = m - mh * 7;
        int ri = (lh - mh + 6) * 13 + (lw - mw + 6);
        v = bias[ri * 16 + h] + mask[(win * 49 + l) * 49 + m];
    }
    bm[idx] = v;
}

// ---------------------------------------------------------------------------
// fp16 GEMM (R10-proven): C[M,N] = A[M,K] * Bt[N,K]^T, fp32 accumulate.
// BM=BN=128, BK=64 halves (128B rows), 3 stages x 32 KB dynamic smem,
// 256 threads (8 warps, 2m x 4n), warp tile 64x32, mma.m16n8k16.
// SW128 swizzle u ^ (row & 7); single barrier per k-tile.
// ---------------------------------------------------------------------------
#define GSTG_B 32768
#define GB_HALF 16384
#define GSMEM (3 * GSTG_B)

template <bool OUT_HALF>
__global__ __launch_bounds__(256, 2)
void gemm_h(const __half* __restrict__ A, const __half* __restrict__ Bt,
            void* __restrict__ Cv, int M, int N, int K) {
    extern __shared__ __align__(16) char dsm[];

    const int tid = threadIdx.x, lane = tid & 31, warp = tid >> 5;
    const int wm = warp >> 2, wn = warp & 3;
    const int m0 = blockIdx.y * 128, n0 = blockIdx.x * 128;

    const int r_ld = tid >> 1;
    const int cb   = (tid & 1) * 4;
    const __half* ag = A  + (size_t)(m0 + r_ld) * K + cb * 8;
    const __half* bg = Bt + (size_t)(n0 + r_ld) * K + cb * 8;
    uint32_t adst[4], bdst[4];
    #pragma unroll
    for (int j = 0; j < 4; ++j) {
        adst[j] = (uint32_t)(r_ld * 128 + (((cb + j) ^ (r_ld & 7)) << 4));
        bdst[j] = GB_HALF + adst[j];
    }

    uint32_t sb[3];
    #pragma unroll
    for (int s = 0; s < 3; ++s) sb[s] = smem_u32(dsm) + s * GSTG_B;

    const int rr = lane & 7;
    const int mA = (lane >> 3) & 1;
    const int kU = lane >> 4;

    float acc[16][4];
    #pragma unroll
    for (int i = 0; i < 16; ++i)
        #pragma unroll
        for (int j = 0; j < 4; ++j) acc[i][j] = 0.f;

    const int nK = K >> 6;

    #pragma unroll
    for (int p = 0; p < 2; ++p) {
        #pragma unroll
        for (int j = 0; j < 4; ++j) {
            cp_async16(sb[p] + adst[j], ag + p * 64 + j * 8);
            cp_async16(sb[p] + bdst[j], bg + p * 64 + j * 8);
        }
        CP_COMMIT();
    }

    for (int kt = 0; kt < nK; ++kt) {
        if (kt + 1 < nK) asm volatile("cp.async.wait_group 1;" ::: "memory");
        else             asm volatile("cp.async.wait_group 0;" ::: "memory");
        __syncthreads();

        if (kt + 2 < nK) {
            uint32_t so = sb[(kt + 2) % 3];
            #pragma unroll
            for (int j = 0; j < 4; ++j) {
                cp_async16(so + adst[j], ag + (kt + 2) * 64 + j * 8);
                cp_async16(so + bdst[j], bg + (kt + 2) * 64 + j * 8);
            }
            CP_COMMIT();
        }

        const uint32_t aB = sb[kt % 3];
        const uint32_t bB = aB + GB_HALF;

        #pragma unroll
        for (int ks = 0; ks < 4; ++ks) {
            uint32_t af[4][4];
            #pragma unroll
            for (int mt = 0; mt < 4; ++mt) {
                int r = wm * 64 + mt * 16 + mA * 8 + rr;
                int u = ks * 2 + kU;
                ldsm_x4(aB + (uint32_t)(r * 128 + ((u ^ (r & 7)) << 4)),
                        af[mt][0], af[mt][1], af[mt][2], af[mt][3]);
            }
            uint32_t bf[2][4];
            #pragma unroll
            for (int p = 0; p < 2; ++p) {
                int n = wn * 32 + p * 16 + kU * 8 + rr;
                int u = ks * 2 + mA;
                ldsm_x4(bB + (uint32_t)(n * 128 + ((u ^ (n & 7)) << 4)),
                        bf[p][0], bf[p][1], bf[p][2], bf[p][3]);
            }
            #pragma unroll
            for (int mt = 0; mt < 4; ++mt)
                #pragma unroll
                for (int nt = 0; nt < 4; ++nt)
                    MMA_F16(acc[mt * 4 + nt],
                            af[mt][0], af[mt][1], af[mt][2], af[mt][3],
                            bf[nt >> 1][(nt & 1) * 2], bf[nt >> 1][(nt & 1) * 2 + 1]);
        }
    }

    const int g = lane >> 2, t = lane & 3;
    #pragma unroll
    for (int mt = 0; mt < 4; ++mt) {
        #pragma unroll
        for (int nt = 0; nt < 4; ++nt) {
            const float* c = acc[mt * 4 + nt];
            int r = m0 + wm * 64 + mt * 16 + g;
            int cc = n0 + wn * 32 + nt * 8 + t * 2;
            if (OUT_HALF) {
                __half* C = (__half*)Cv;
                *(__half2*)&C[(size_t)r * N + cc]       = __floats2half2_rn(c[0], c[1]);
                *(__half2*)&C[(size_t)(r + 8) * N + cc] = __floats2half2_rn(c[2], c[3]);
            } else {
                float* C = (float*)Cv;
                *(float2*)&C[(size_t)r * N + cc]       = make_float2(c[0], c[1]);
                *(float2*)&C[(size_t)(r + 8) * N + cc] = make_float2(c[2], c[3]);
            }
        }
    }
}

// ---------------------------------------------------------------------------
// fp16 tensor-core attention (R11-proven: cp.async zfill QKV, trans-ldmatrix V).
// One CTA per (window b, head h); 128 threads, 4 warps.
// Smem: Q [64][64B] @0, K @4096, V [64][64B] @8192 (row-major), P [64][144B] @12288.
// ---------------------------------------------------------------------------
#define QO 0
#define KO 4096
#define VO 8192
#define PO 12288
#define ATT_SMEM (12288 + 64 * 144)

__global__ __launch_bounds__(128, 6)
void attn_h(const __half* __restrict__ qkv, const float* __restrict__ bm,
            __half* __restrict__ att) {
    __shared__ __align__(16) char smc[ATT_SMEM];
    const uint32_t sb = smem_u32(smc);

    const int b = blockIdx.x, h = blockIdx.y;
    const int tid = threadIdx.x, lane = tid & 31, w = tid >> 5;

    const __half* base = qkv + (size_t)b * L_TOK * 1536 + h * HD_DIM;

    #pragma unroll
    for (int j = 0; j < 2; ++j) {
        int u = tid * 2 + j;
        int r = u >> 2, c = u & 3;
        uint32_t sz = (r < L_TOK) ? 16u : 0u;
        const __half* src = (r < L_TOK) ? (base + (size_t)r * 1536 + c * 8) : base;
        uint32_t dst = (uint32_t)(r * 64 + ((c ^ ((r >> 1) & 3)) << 4));
        cp_async16z(sb + QO + dst, src, sz);
        cp_async16z(sb + KO + dst, src + 512, sz);
        cp_async16z(sb + VO + dst, src + 1024, sz);
    }
    CP_COMMIT();
    asm volatile("cp.async.wait_group 0;" ::: "memory");
    __syncthreads();

    const int rr = lane & 7;
    const int mA = (lane >> 3) & 1;
    const int kU = lane >> 4;

    float sacc[8][4];
    #pragma unroll
    for (int j = 0; j < 8; ++j)
        #pragma unroll
        for (int r = 0; r < 4; ++r) sacc[j][r] = 0.f;

    #pragma unroll
    for (int ks = 0; ks < 2; ++ks) {
        uint32_t a[4];
        {
            int r = w * 16 + mA * 8 + rr;
            int u = ks * 2 + kU;
            ldsm_x4(sb + QO + (uint32_t)(r * 64 + ((u ^ ((r >> 1) & 3)) << 4)),
                    a[0], a[1], a[2], a[3]);
        }
        uint32_t bf[4][4];
        #pragma unroll
        for (int p = 0; p < 4; ++p) {
            int n = p * 16 + kU * 8 + rr;
            int u = ks * 2 + mA;
            ldsm_x4(sb + KO + (uint32_t)(n * 64 + ((u ^ ((n >> 1) & 3)) << 4)),
                    bf[p][0], bf[p][1], bf[p][2], bf[p][3]);
        }
        #pragma unroll
        for (int nt = 0; nt < 8; ++nt)
            MMA_F16(sacc[nt], a[0], a[1], a[2], a[3],
                    bf[nt >> 1][(nt & 1) * 2], bf[nt >> 1][(nt & 1) * 2 + 1]);
    }

    const int g = lane >> 2, t = lane & 3;
    const int l0 = w * 16 + g, l1 = l0 + 8;
    const int win = b & 63;
    const bool v0 = (l0 < L_TOK), v1 = (l1 < L_TOK);
    const int l0c = v0 ? l0 : 48, l1c = v1 ? l1 : 48;
    const float* bm0 = bm + (((size_t)win * 16 + h) * 49 + l0c) * 56;
    const float* bm1 = bm + (((size_t)win * 16 + h) * 49 + l1c) * 56;
    const float scale = 0.1767766952966369f;

    float mx0 = -1e30f, mx1 = -1e30f;
    #pragma unroll
    for (int j = 0; j < 8; ++j) {
        int ma = 8 * j + 2 * t;
        float* c = sacc[j];
        if (ma < L_TOK) {
            float2 ba = *(const float2*)&bm0[ma];
            float2 bb = *(const float2*)&bm1[ma];
            c[0] = v0 ? fmaf(c[0], scale, ba.x) : -1e30f;
            c[1] = (v0 && ma + 1 < L_TOK) ? fmaf(c[1], scale, ba.y) : -1e30f;
            c[2] = v1 ? fmaf(c[2], scale, bb.x) : -1e30f;
            c[3] = (v1 && ma + 1 < L_TOK) ? fmaf(c[3], scale, bb.y) : -1e30f;
        } else {
            c[0] = c[1] = c[2] = c[3] = -1e30f;
        }
        mx0 = fmaxf(mx0, fmaxf(c[0], c[1]));
        mx1 = fmaxf(mx1, fmaxf(c[2], c[3]));
    }
    mx0 = fmaxf(mx0, __shfl_xor_sync(0xffffffffu, mx0, 1));
    mx0 = fmaxf(mx0, __shfl_xor_sync(0xffffffffu, mx0, 2));
    mx1 = fmaxf(mx1, __shfl_xor_sync(0xffffffffu, mx1, 1));
    mx1 = fmaxf(mx1, __shfl_xor_sync(0xffffffffu, mx1, 2));

    float s0 = 0.f, s1 = 0.f;
    #pragma unroll
    for (int j = 0; j < 8; ++j) {
        float* c = sacc[j];
        c[0] = __expf(c[0] - mx0);
        c[1] = __expf(c[1] - mx0);
        c[2] = __expf(c[2] - mx1);
        c[3] = __expf(c[3] - mx1);
        s0 += c[0] + c[1];
        s1 += c[2] + c[3];
    }
    s0 += __shfl_xor_sync(0xffffffffu, s0, 1);
    s0 += __shfl_xor_sync(0xffffffffu, s0, 2);
    s1 += __shfl_xor_sync(0xffffffffu, s1, 1);
    s1 += __shfl_xor_sync(0xffffffffu, s1, 2);
    const float i0 = 1.f / s0, i1 = 1.f / s1;

    #pragma unroll
    for (int j = 0; j < 8; ++j) {
        float* c = sacc[j];
        int col = 8 * j + 2 * t;
        *(__half2*)(smc + PO + l0 * 144 + col * 2) = __floats2half2_rn(c[0] * i0, c[1] * i0);
        *(__half2*)(smc + PO + l1 * 144 + col * 2) = __floats2half2_rn(c[2] * i1, c[3] * i1);
    }
    __syncwarp();

    float oacc[4][4];
    #pragma unroll
    for (int nt = 0; nt < 4; ++nt)
        #pragma unroll
        for (int r = 0; r < 4; ++r) oacc[nt][r] = 0.f;

    #pragma unroll
    for (int ks = 0; ks < 4; ++ks) {
        uint32_t a[4];
        {
            int r = w * 16 + mA * 8 + rr;
            int u = ks * 2 + kU;
            ldsm_x4(sb + PO + (uint32_t)(r * 144 + u * 16), a[0], a[1], a[2], a[3]);
        }
        uint32_t bf[2][4];
        #pragma unroll
        for (int p = 0; p < 2; ++p) {
            int vr = ks * 16 + mA * 8 + rr;
            int u  = p * 2 + kU;
            ldsm_x4_t(sb + VO + (uint32_t)(vr * 64 + ((u ^ ((vr >> 1) & 3)) << 4)),
                      bf[p][0], bf[p][1], bf[p][2], bf[p][3]);
        }
        #pragma unroll
        for (int nt = 0; nt < 4; ++nt)
            MMA_F16(oacc[nt], a[0], a[1], a[2], a[3],
                    bf[nt >> 1][(nt & 1) * 2], bf[nt >> 1][(nt & 1) * 2 + 1]);
    }

    __half* orow0 = att + ((size_t)b * L_TOK + l0) * C_DIM + h * HD_DIM;
    __half* orow1 = orow0 + (size_t)8 * C_DIM;
    #pragma unroll
    for (int nt = 0; nt < 4; ++nt) {
        int d = nt * 8 + t * 2;
        if (v0) *(__half2*)(orow0 + d) = __floats2half2_rn(oacc[nt][0], oacc[nt][1]);
        if (v1) *(__half2*)(orow1 + d) = __floats2half2_rn(oacc[nt][2], oacc[nt][3]);
    }
}

// ---------------------------------------------------------------------------
// kernel_launch
// ---------------------------------------------------------------------------
extern "C" void kernel_launch(void* const* d_in, const int* in_sizes, int n_in,
                              void* d_out, int out_size) {
    const float* x     = (const float*)d_in[0];
    const float* mask  = (const float*)d_in[1];
    const float* bias  = (const float*)d_in[2];
    const float* wqkv  = (const float*)d_in[3];
    const float* wproj = (const float*)d_in[4];
    float*       out   = (float*)d_out;

    void *xh, *qkvh, *atth, *wqkvth, *wprojth, *bm;
    cudaGetSymbolAddress(&xh, g_xh);
    cudaGetSymbolAddress(&qkvh, g_qkvh);
    cudaGetSymbolAddress(&atth, g_atth);
    cudaGetSymbolAddress(&wqkvth, g_wqkvth);
    cudaGetSymbolAddress(&wprojth, g_wprojth);
    cudaGetSymbolAddress(&bm, g_bm);

    cudaFuncSetAttribute(gemm_h<true>,  cudaFuncAttributeMaxDynamicSharedMemorySize, GSMEM);
    cudaFuncSetAttribute(gemm_h<false>, cudaFuncAttributeMaxDynamicSharedMemorySize, GSMEM);

    // 0) Pre-passes
    const int n4 = ROWS * C_DIM / 4;
    f32_to_f16<<<(n4 + 255) / 256, 256>>>((const float4*)x, (__half2*)xh, n4);
    transpose_h<<<dim3(1536 / 32, 512 / 32), dim3(32, 8)>>>(wqkv, (__half*)wqkvth, C_DIM, 3 * C_DIM);
    transpose_h<<<dim3(512 / 32, 512 / 32), dim3(32, 8)>>>(wproj, (__half*)wprojth, C_DIM, C_DIM);
    const int bmTot = 64 * 16 * 49 * 56;
    build_bm<<<(bmTot + 255) / 256, 256>>>(mask, bias, (float*)bm);

    // 1) QKV projection
    gemm_h<true><<<dim3(1536 / 128, ROWS / 128), 256, GSMEM>>>(
        (const __half*)xh, (const __half*)wqkvth, qkvh, ROWS, 3 * C_DIM, C_DIM);

    // 2) Windowed attention
    attn_h<<<dim3(B_TOT, H_HEADS), 128>>>((const __half*)qkvh, (const float*)bm, (__half*)atth);

    // 3) Output projection (fp32 out)
    gemm_h<false><<<dim3(C_DIM / 128, ROWS / 128), 256, GSMEM>>>(
        (const __half*)atth, (const __half*)wprojth, out, ROWS, C_DIM, C_DIM);
}